// round 2
// baseline (speedup 1.0000x reference)
#include <cuda_runtime.h>
#include <cuda_bf16.h>

#define NN 50000
#define EE 600000
#define GG 512
#define CHN 128
#define BN_EPS 1e-5f

// ---------------- scratch (device globals; allocation-free) ----------------
__device__ int   g_counts[NN];
__device__ int   g_cursor[NN];
__device__ int   g_offsets[NN + 1];
__device__ int   g_csr[EE];
__device__ int   g_gcnt[GG];
__device__ int   g_goff[GG + 1];
__device__ float g_t[NN * CHN];     // x + agg
__device__ float g_u[NN * CHN];     // relu(BN(t@W1+b1))
__device__ float g_x1[NN * CHN];
__device__ float g_x2[NN * CHN];
__device__ float g_x3[NN * CHN];
__device__ float g_pooled[GG * 384];

__device__ __forceinline__ float* buf_ptr(int s) {
    switch (s) {
        case 0: return g_t;
        case 1: return g_u;
        case 2: return g_x1;
        case 3: return g_x2;
        default: return g_x3;
    }
}

// ---------------- CSR build ----------------
__global__ void zero_k() {
    int i = blockIdx.x * blockDim.x + threadIdx.x;
    if (i < NN) { g_counts[i] = 0; g_cursor[i] = 0; }
    if (i < GG) g_gcnt[i] = 0;
}

__global__ void hist_dst_k(const int* __restrict__ ei) {
    int e = blockIdx.x * blockDim.x + threadIdx.x;
    if (e < EE) atomicAdd(&g_counts[ei[EE + e]], 1);
}

__global__ void hist_batch_k(const int* __restrict__ batch) {
    int i = blockIdx.x * blockDim.x + threadIdx.x;
    if (i < NN) atomicAdd(&g_gcnt[batch[i]], 1);
}

// single-block exclusive scan, thread-coarsened by 8
template <int SEL>
__global__ void scan_k(int n) {
    const int* counts = (SEL == 0) ? g_counts : g_gcnt;
    int* offsets      = (SEL == 0) ? g_offsets : g_goff;
    __shared__ int sh[1024];
    __shared__ int carrysh;
    int tid = threadIdx.x;
    if (tid == 0) carrysh = 0;
    __syncthreads();
    const int CHK = 1024 * 8;
    for (int base = 0; base < n; base += CHK) {
        int vals[8];
        int tsum = 0;
#pragma unroll
        for (int j = 0; j < 8; j++) {
            int idx = base + tid * 8 + j;
            int v = (idx < n) ? counts[idx] : 0;
            vals[j] = tsum;             // local exclusive prefix
            tsum += v;
        }
        sh[tid] = tsum;
        __syncthreads();
        for (int off = 1; off < 1024; off <<= 1) {
            int v = (tid >= off) ? sh[tid - off] : 0;
            __syncthreads();
            sh[tid] += v;
            __syncthreads();
        }
        int incl = sh[tid];
        int excl = incl - tsum;
        int c = carrysh;
        __syncthreads();
#pragma unroll
        for (int j = 0; j < 8; j++) {
            int idx = base + tid * 8 + j;
            if (idx < n) offsets[idx] = c + excl + vals[j];
        }
        if (tid == 1023) carrysh = c + incl;
        __syncthreads();
    }
    if (tid == 0) offsets[n] = carrysh;
}

__global__ void fill_csr_k(const int* __restrict__ ei) {
    int e = blockIdx.x * blockDim.x + threadIdx.x;
    if (e < EE) {
        int s = ei[e];
        int d = ei[EE + e];
        int pos = atomicAdd(&g_cursor[d], 1);
        g_csr[g_offsets[d] + pos] = s;
    }
}

// ---------------- aggregation: t[i] = x[i] + sum_{j in N(i)} x[j] ----------------
// one warp per node; lane handles 4 contiguous floats (float4)
__global__ void aggregate_k(const float* __restrict__ xext, int sel) {
    int node = blockIdx.x * 8 + (threadIdx.x >> 5);
    int lane = threadIdx.x & 31;
    if (node >= NN) return;
    const float* x = (sel < 0) ? xext : buf_ptr(sel);
    const float4* x4 = (const float4*)x;
    float4 acc = x4[node * 32 + lane];
    int s = g_offsets[node];
    int e = g_offsets[node + 1];
    for (int p = s; p < e; p++) {
        int src = g_csr[p];
        float4 v = __ldg(&x4[src * 32 + lane]);
        acc.x += v.x; acc.y += v.y; acc.z += v.z; acc.w += v.w;
    }
    ((float4*)g_t)[node * 32 + lane] = acc;
}

// ---------------- GEMM: out[n,128] = epi(A[n,128] @ W[128,128]) ----------------
// MODE 0: BN fold + ReLU   (p0=b1, p1=gm, p2=bt, p3=rm, p4=rv)
// MODE 1: +bias, ReLU      (p0=b2)
// MODE 2: +bias            (p0=b2)
// block: 256 thr, tile 128 rows x 64 cols (blockIdx.y = column half)
// thread tile 4 rows x 8 cols. smem: W half 128x64 (32KB) + A tile 128x8 pad 9.
template <int MODE>
__global__ __launch_bounds__(256) void gemm128_k(
    int aSel, int outSel,
    const float* __restrict__ W,
    const float* __restrict__ p0, const float* __restrict__ p1,
    const float* __restrict__ p2, const float* __restrict__ p3,
    const float* __restrict__ p4, int n)
{
    __shared__ float Ws[128 * 64];      // Ws[k][c] = W[k*128 + half*64 + c]
    __shared__ float As[128 * 9];       // pad-9: banks distinct for rows {i,4+i,8+i,12+i}

    const float* A = buf_ptr(aSel);
    float* out = buf_ptr(outSel);

    int tid  = threadIdx.x;
    int half = blockIdx.y;              // 0 or 1
    int rowBase = blockIdx.x * 128;

    // cooperative load of W half: 8192 floats = 2048 float4 = 8 per thread
    {
        const float4* W4 = (const float4*)W;   // global row = 32 float4
        float4* Ws4 = (float4*)Ws;             // smem row  = 16 float4
#pragma unroll
        for (int i = 0; i < 8; i++) {
            int idx = tid + 256 * i;           // 0..2047
            int kr = idx >> 4;                 // 0..127
            int c4 = idx & 15;                 // 0..15
            Ws4[kr * 16 + c4] = W4[kr * 32 + half * 16 + c4];
        }
    }

    int tx = tid & 7;      // col group: cols tx*8 .. tx*8+7 (within 64)
    int ty = tid >> 3;     // row group: rows ty*4 .. ty*4+3 (within 128)

    float acc[4][8];
#pragma unroll
    for (int i = 0; i < 4; i++)
#pragma unroll
        for (int j = 0; j < 8; j++) acc[i][j] = 0.f;

    const float4* Ws4 = (const float4*)Ws;

    for (int kt = 0; kt < 128; kt += 8) {
        // stage A tile 128x8: one float4 per thread
        int r  = tid >> 1;           // 0..127
        int kk = (tid & 1) * 4;      // 0 or 4
        int grow = rowBase + r;
        float4 av = (grow < n) ? *(const float4*)&A[grow * 128 + kt + kk]
                               : make_float4(0.f, 0.f, 0.f, 0.f);
        __syncthreads();
        As[r * 9 + kk + 0] = av.x;
        As[r * 9 + kk + 1] = av.y;
        As[r * 9 + kk + 2] = av.z;
        As[r * 9 + kk + 3] = av.w;
        __syncthreads();
#pragma unroll
        for (int k = 0; k < 8; k++) {
            float4 w0 = Ws4[(kt + k) * 16 + tx * 2];
            float4 w1 = Ws4[(kt + k) * 16 + tx * 2 + 1];
#pragma unroll
            for (int i = 0; i < 4; i++) {
                float a = As[(ty * 4 + i) * 9 + k];
                acc[i][0] += a * w0.x; acc[i][1] += a * w0.y;
                acc[i][2] += a * w0.z; acc[i][3] += a * w0.w;
                acc[i][4] += a * w1.x; acc[i][5] += a * w1.y;
                acc[i][6] += a * w1.z; acc[i][7] += a * w1.w;
            }
        }
    }

    // epilogue
    int c0 = half * 64 + tx * 8;
    float alpha[8], beta[8];
#pragma unroll
    for (int j = 0; j < 8; j++) {
        int c = c0 + j;
        if (MODE == 0) {
            float s = rsqrtf(p4[c] + BN_EPS);
            float a = p1[c] * s;
            alpha[j] = a;
            beta[j] = (p0[c] - p3[c]) * a + p2[c];
        } else {
            alpha[j] = 1.f;
            beta[j] = p0[c];
        }
    }
#pragma unroll
    for (int i = 0; i < 4; i++) {
        int grow = rowBase + ty * 4 + i;
        if (grow < n) {
            float v[8];
#pragma unroll
            for (int j = 0; j < 8; j++) {
                float t = acc[i][j] * alpha[j] + beta[j];
                if (MODE < 2) t = fmaxf(t, 0.f);
                v[j] = t;
            }
            *(float4*)&out[grow * 128 + c0]     = make_float4(v[0], v[1], v[2], v[3]);
            *(float4*)&out[grow * 128 + c0 + 4] = make_float4(v[4], v[5], v[6], v[7]);
        }
    }
}

// ---------------- pooling (mean over each graph's contiguous node range) ----------------
__global__ void pool_k() {
    int g = blockIdx.x;
    int tid = threadIdx.x;   // 128
    int s = g_goff[g];
    int e = g_goff[g + 1];
    float a1 = 0.f, a2 = 0.f, a3 = 0.f;
    for (int i = s; i < e; i++) {
        a1 += g_x1[i * 128 + tid];
        a2 += g_x2[i * 128 + tid];
        a3 += g_x3[i * 128 + tid];
    }
    float inv = 1.0f / (float)max(e - s, 1);
    g_pooled[g * 384 + tid]       = a1 * inv;
    g_pooled[g * 384 + 128 + tid] = a2 * inv;
    g_pooled[g * 384 + 256 + tid] = a3 * inv;
}

// ---------------- final linear: out[512,128] = pooled[512,384] @ lin_W + lin_b ----------------
__global__ void fin_k(const float* __restrict__ W, const float* __restrict__ b,
                      float* __restrict__ out) {
    __shared__ float p[384];
    int g = blockIdx.x;
    int tid = threadIdx.x;   // 128
    for (int i = tid; i < 384; i += 128) p[i] = g_pooled[g * 384 + i];
    __syncthreads();
    float acc = b[tid];
#pragma unroll 4
    for (int k = 0; k < 384; k++) acc += p[k] * W[k * 128 + tid];
    out[g * 128 + tid] = acc;
}

// ---------------- launch ----------------
extern "C" void kernel_launch(void* const* d_in, const int* in_sizes, int n_in,
                              void* d_out, int out_size) {
    const float* x     = (const float*)d_in[0];
    const int*   ei    = (const int*)d_in[1];     // int64 in ref -> delivered as int32
    const int*   batch = (const int*)d_in[2];
    float* out = (float*)d_out;

    // per-layer params start at index 3, 8 tensors each:
    // W1, b1, gm, bt, rm, rv, W2, b2
    const float* L[3][8];
    for (int l = 0; l < 3; l++)
        for (int k = 0; k < 8; k++)
            L[l][k] = (const float*)d_in[3 + l * 8 + k];
    const float* linW = (const float*)d_in[27];
    const float* linB = (const float*)d_in[28];

    dim3 gemmGrid((NN + 127) / 128, 2);   // 391 x 2

    zero_k<<<(NN + 255) / 256, 256>>>();
    hist_dst_k<<<(EE + 255) / 256, 256>>>(ei);
    scan_k<0><<<1, 1024>>>(NN);
    fill_csr_k<<<(EE + 255) / 256, 256>>>(ei);
    hist_batch_k<<<(NN + 255) / 256, 256>>>(batch);
    scan_k<1><<<1, 1024>>>(GG);

    // layer 1: x -> t -> u -> x1 (outer ReLU)
    aggregate_k<<<(NN + 7) / 8, 256>>>(x, -1);
    gemm128_k<0><<<gemmGrid, 256>>>(0, 1, L[0][0], L[0][1], L[0][2], L[0][3], L[0][4], L[0][5], NN);
    gemm128_k<1><<<gemmGrid, 256>>>(1, 2, L[0][6], L[0][7], nullptr, nullptr, nullptr, nullptr, NN);

    // layer 2: x1 -> t -> u -> x2 (outer ReLU)
    aggregate_k<<<(NN + 7) / 8, 256>>>(nullptr, 2);
    gemm128_k<0><<<gemmGrid, 256>>>(0, 1, L[1][0], L[1][1], L[1][2], L[1][3], L[1][4], L[1][5], NN);
    gemm128_k<1><<<gemmGrid, 256>>>(1, 3, L[1][6], L[1][7], nullptr, nullptr, nullptr, nullptr, NN);

    // layer 3: x2 -> t -> u -> x3 (no outer ReLU)
    aggregate_k<<<(NN + 7) / 8, 256>>>(nullptr, 3);
    gemm128_k<0><<<gemmGrid, 256>>>(0, 1, L[2][0], L[2][1], L[2][2], L[2][3], L[2][4], L[2][5], NN);
    gemm128_k<2><<<gemmGrid, 256>>>(1, 4, L[2][6], L[2][7], nullptr, nullptr, nullptr, nullptr, NN);

    pool_k<<<GG, 128>>>();
    fin_k<<<GG, 128>>>(linW, linB, out);
}

// round 6
// speedup vs baseline: 1.5801x; 1.5801x over previous
#include <cuda_runtime.h>
#include <cuda_bf16.h>
#include <cstdint>

#define NN 50000
#define EE 600000
#define GG 512
#define BN_EPS 1e-5f

// ================= scratch (device globals; allocation-free) =================
__device__ int   g_counts[NN];
__device__ int   g_cursor[NN];
__device__ int   g_offsets[NN + 1];
__device__ int   g_csr[EE];
__device__ int   g_gcnt[GG];
__device__ int   g_goff[GG + 1];
__device__ __nv_bfloat16 g_ahi[NN * 128], g_alo[NN * 128];   // GEMM1 input pair
__device__ __nv_bfloat16 g_bhi[NN * 128], g_blo[NN * 128];   // GEMM2 input pair
__device__ float g_x1[NN * 128], g_x2[NN * 128], g_x3[NN * 128];
__device__ float g_pooled[GG * 384];
// transposed hi/lo weights: g_wh[m][n*128+k] = hi(W_m[k][n])
__device__ __nv_bfloat16 g_wh[6 * 16384], g_wl[6 * 16384];

// device-side buffer resolution (NEVER pass __device__ symbols from host!)
__device__ __forceinline__ float* xbuf(int s) {
    return (s == 1) ? g_x1 : (s == 2) ? g_x2 : g_x3;
}

__device__ __forceinline__ uint32_t bfpack(__nv_bfloat16 a, __nv_bfloat16 b) {
    return (uint32_t)__bfloat16_as_ushort(a) | ((uint32_t)__bfloat16_as_ushort(b) << 16);
}

// mma.sync m16n8k16 bf16 -> f32 accumulate (baseline PTX, compiles for sm_103)
__device__ __forceinline__ void mma16816(float* c, const uint32_t* a, uint32_t b0, uint32_t b1) {
    asm volatile(
        "mma.sync.aligned.m16n8k16.row.col.f32.bf16.bf16.f32 "
        "{%0,%1,%2,%3}, {%4,%5,%6,%7}, {%8,%9}, {%0,%1,%2,%3};"
        : "+f"(c[0]), "+f"(c[1]), "+f"(c[2]), "+f"(c[3])
        : "r"(a[0]), "r"(a[1]), "r"(a[2]), "r"(a[3]), "r"(b0), "r"(b1));
}

// ================= CSR build =================
__global__ void zero_k() {
    int i = blockIdx.x * blockDim.x + threadIdx.x;
    if (i < NN) { g_counts[i] = 0; g_cursor[i] = 0; }
    if (i < GG) g_gcnt[i] = 0;
}
__global__ void hist_dst_k(const int* __restrict__ ei) {
    int e = blockIdx.x * blockDim.x + threadIdx.x;
    if (e < EE) atomicAdd(&g_counts[ei[EE + e]], 1);
}
__global__ void hist_batch_k(const int* __restrict__ batch) {
    int i = blockIdx.x * blockDim.x + threadIdx.x;
    if (i < NN) atomicAdd(&g_gcnt[batch[i]], 1);
}
template <int SEL>
__global__ void scan_k(int n) {
    const int* counts = (SEL == 0) ? g_counts : g_gcnt;
    int* offsets      = (SEL == 0) ? g_offsets : g_goff;
    __shared__ int sh[1024];
    __shared__ int carrysh;
    int tid = threadIdx.x;
    if (tid == 0) carrysh = 0;
    __syncthreads();
    const int CHK = 1024 * 8;
    for (int base = 0; base < n; base += CHK) {
        int vals[8];
        int tsum = 0;
#pragma unroll
        for (int j = 0; j < 8; j++) {
            int idx = base + tid * 8 + j;
            int v = (idx < n) ? counts[idx] : 0;
            vals[j] = tsum;
            tsum += v;
        }
        sh[tid] = tsum;
        __syncthreads();
        for (int off = 1; off < 1024; off <<= 1) {
            int v = (tid >= off) ? sh[tid - off] : 0;
            __syncthreads();
            sh[tid] += v;
            __syncthreads();
        }
        int incl = sh[tid];
        int excl = incl - tsum;
        int c = carrysh;
        __syncthreads();
#pragma unroll
        for (int j = 0; j < 8; j++) {
            int idx = base + tid * 8 + j;
            if (idx < n) offsets[idx] = c + excl + vals[j];
        }
        if (tid == 1023) carrysh = c + incl;
        __syncthreads();
    }
    if (tid == 0) offsets[n] = carrysh;
}
__global__ void fill_csr_k(const int* __restrict__ ei) {
    int e = blockIdx.x * blockDim.x + threadIdx.x;
    if (e < EE) {
        int s = ei[e];
        int d = ei[EE + e];
        int pos = atomicAdd(&g_cursor[d], 1);
        g_csr[g_offsets[d] + pos] = s;
    }
}

// ================= weight prep: transpose + hi/lo split =================
__global__ void prep_w_k(const float* w0, const float* w1, const float* w2,
                         const float* w3, const float* w4, const float* w5) {
    const float* Ws[6] = {w0, w1, w2, w3, w4, w5};
    int m = blockIdx.x;
    const float* W = Ws[m];
    for (int i = threadIdx.x; i < 16384; i += blockDim.x) {
        int n = i >> 7;          // output column (B row)
        int k = i & 127;         // contraction
        float v = W[k * 128 + n];
        __nv_bfloat16 hi = __float2bfloat16(v);
        __nv_bfloat16 lo = __float2bfloat16(v - __bfloat162float(hi));
        g_wh[m * 16384 + i] = hi;
        g_wl[m * 16384 + i] = lo;
    }
}

// ================= aggregation: pair = split(x[i] + sum_{j in N(i)} x[j]) =================
// sel < 0: use external x; else g_x<sel>
__global__ void aggregate_k(const float* __restrict__ xext, int sel) {
    int node = blockIdx.x * 8 + (threadIdx.x >> 5);
    int lane = threadIdx.x & 31;
    if (node >= NN) return;
    const float* x = (sel < 0) ? xext : xbuf(sel);
    const float4* x4 = (const float4*)x;
    float4 acc = x4[node * 32 + lane];
    int s = g_offsets[node];
    int e = g_offsets[node + 1];
    for (int p = s; p < e; p++) {
        float4 v = __ldg(&x4[g_csr[p] * 32 + lane]);
        acc.x += v.x; acc.y += v.y; acc.z += v.z; acc.w += v.w;
    }
    float vv[4] = {acc.x, acc.y, acc.z, acc.w};
    __nv_bfloat16 h[4], l[4];
#pragma unroll
    for (int j = 0; j < 4; j++) {
        h[j] = __float2bfloat16(vv[j]);
        l[j] = __float2bfloat16(vv[j] - __bfloat162float(h[j]));
    }
    int base = node * 128 + lane * 4;
    *(uint2*)(g_ahi + base) = make_uint2(bfpack(h[0], h[1]), bfpack(h[2], h[3]));
    *(uint2*)(g_alo + base) = make_uint2(bfpack(l[0], l[1]), bfpack(l[2], l[3]));
}

// ================= tensor-core GEMM via mma.sync =================
// D[128x128] = Ahi@Wh + Ahi@Wl + Alo@Wh  (fp32 accum), per-CTA row tile of 128.
// inSel: 0 -> (g_ahi, g_alo), 1 -> (g_bhi, g_blo)
// MODE 0: BN fold + ReLU -> writes bf16 pair (g_bhi, g_blo)
// MODE 1: +bias, ReLU    -> writes fp32 xbuf(outSel)
// MODE 2: +bias          -> writes fp32 xbuf(outSel)
#define SW 136   // W smem stride (bf16)
#define SA 40    // A smem stride (bf16)

template <int MODE>
__global__ __launch_bounds__(256, 2) void gemm_tc_k(
    int inSel, int outSel, int wsel,
    const float* __restrict__ p0, const float* __restrict__ p1,
    const float* __restrict__ p2, const float* __restrict__ p3,
    const float* __restrict__ p4, int n)
{
    extern __shared__ char dyn[];
    __nv_bfloat16* Whs = (__nv_bfloat16*)dyn;                         // 128*SW
    __nv_bfloat16* Wls = (__nv_bfloat16*)(dyn + 128 * SW * 2);        // 128*SW
    __nv_bfloat16* Ahs = (__nv_bfloat16*)(dyn + 2 * 128 * SW * 2);    // 128*SA
    __nv_bfloat16* Als = (__nv_bfloat16*)(dyn + 2 * 128 * SW * 2 + 128 * SA * 2);
    __shared__ float s_alpha[128], s_beta[128];

    const __nv_bfloat16* Ahi = inSel ? g_bhi : g_ahi;
    const __nv_bfloat16* Alo = inSel ? g_blo : g_alo;
    float* outF = (MODE == 0) ? nullptr : xbuf(outSel);

    int tid = threadIdx.x;
    int lane = tid & 31;
    int wid = tid >> 5;
    int warpM = wid & 3;        // 4 row-warps * 32 rows
    int warpN = wid >> 2;       // 2 col-warps * 64 cols
    int blockRow = blockIdx.x * 128;

    // ---- stage W (transposed [n][k]) into smem: 16 uint4 per row, 2 thr/row x 8 each ----
    {
        const uint4* whG = (const uint4*)(g_wh + wsel * 16384);
        const uint4* wlG = (const uint4*)(g_wl + wsel * 16384);
        int r = tid >> 1;              // row n (0..127)
        int h = tid & 1;               // k half
#pragma unroll
        for (int i = 0; i < 8; i++) {
            int q = h * 8 + i;         // uint4 index in row (16 per row)
            uint4 vh = whG[r * 16 + q];
            uint4 vl = wlG[r * 16 + q];
            *(uint4*)((char*)Whs + r * (SW * 2) + q * 16) = vh;
            *(uint4*)((char*)Wls + r * (SW * 2) + q * 16) = vl;
        }
    }
    if (tid < 128) {
        if (MODE == 0) {
            float s = rsqrtf(p4[tid] + BN_EPS);
            float a = p1[tid] * s;
            s_alpha[tid] = a;
            s_beta[tid] = (p0[tid] - p3[tid]) * a + p2[tid];
        } else {
            s_alpha[tid] = 1.f;
            s_beta[tid] = p0[tid];
        }
    }

    float acc[2][8][4];
#pragma unroll
    for (int mt = 0; mt < 2; mt++)
#pragma unroll
        for (int nt = 0; nt < 8; nt++)
#pragma unroll
            for (int q = 0; q < 4; q++) acc[mt][nt][q] = 0.f;

    for (int kc = 0; kc < 4; kc++) {
        // ---- stage A chunk [128][32] hi+lo ----
        __syncthreads();
        {
            int r = tid >> 1;
            int h = tid & 1;           // 16-bf16 half of the 32-chunk
            int grow = blockRow + r;
            uint4 vh0 = make_uint4(0, 0, 0, 0), vh1 = vh0, vl0 = vh0, vl1 = vh0;
            if (grow < n) {
                const uint4* src_h = (const uint4*)(Ahi + (size_t)grow * 128 + kc * 32 + h * 16);
                const uint4* src_l = (const uint4*)(Alo + (size_t)grow * 128 + kc * 32 + h * 16);
                vh0 = src_h[0]; vh1 = src_h[1];
                vl0 = src_l[0]; vl1 = src_l[1];
            }
            char* dh = (char*)Ahs + r * (SA * 2) + h * 32;
            char* dl = (char*)Als + r * (SA * 2) + h * 32;
            *(uint4*)dh = vh0; *(uint4*)(dh + 16) = vh1;
            *(uint4*)dl = vl0; *(uint4*)(dl + 16) = vl1;
        }
        __syncthreads();

#pragma unroll
        for (int ks = 0; ks < 2; ks++) {
            int kk = ks * 16 + (lane & 3) * 2;     // chunk-local k for A frags
            uint32_t ah[2][4], al[2][4];
#pragma unroll
            for (int mt = 0; mt < 2; mt++) {
                int r = warpM * 32 + mt * 16 + (lane >> 2);
                ah[mt][0] = *(const uint32_t*)&Ahs[r * SA + kk];
                ah[mt][1] = *(const uint32_t*)&Ahs[(r + 8) * SA + kk];
                ah[mt][2] = *(const uint32_t*)&Ahs[r * SA + kk + 8];
                ah[mt][3] = *(const uint32_t*)&Ahs[(r + 8) * SA + kk + 8];
                al[mt][0] = *(const uint32_t*)&Als[r * SA + kk];
                al[mt][1] = *(const uint32_t*)&Als[(r + 8) * SA + kk];
                al[mt][2] = *(const uint32_t*)&Als[r * SA + kk + 8];
                al[mt][3] = *(const uint32_t*)&Als[(r + 8) * SA + kk + 8];
            }
            int kg = kc * 32 + ks * 16 + (lane & 3) * 2;   // global k for B frags
#pragma unroll
            for (int nt = 0; nt < 8; nt++) {
                int nr = warpN * 64 + nt * 8 + (lane >> 2);
                uint32_t bh0 = *(const uint32_t*)&Whs[nr * SW + kg];
                uint32_t bh1 = *(const uint32_t*)&Whs[nr * SW + kg + 8];
                uint32_t bl0 = *(const uint32_t*)&Wls[nr * SW + kg];
                uint32_t bl1 = *(const uint32_t*)&Wls[nr * SW + kg + 8];
#pragma unroll
                for (int mt = 0; mt < 2; mt++) {
                    mma16816(acc[mt][nt], ah[mt], bh0, bh1);
                    mma16816(acc[mt][nt], ah[mt], bl0, bl1);
                    mma16816(acc[mt][nt], al[mt], bh0, bh1);
                }
            }
        }
    }

    // ---- epilogue ----
#pragma unroll
    for (int mt = 0; mt < 2; mt++) {
        int r0 = blockRow + warpM * 32 + mt * 16 + (lane >> 2);
        int r1 = r0 + 8;
#pragma unroll
        for (int nt = 0; nt < 8; nt++) {
            int c = warpN * 64 + nt * 8 + (lane & 3) * 2;
            float a0 = s_alpha[c], a1 = s_alpha[c + 1];
            float b0 = s_beta[c],  b1 = s_beta[c + 1];
            float v00 = acc[mt][nt][0] * a0 + b0;
            float v01 = acc[mt][nt][1] * a1 + b1;
            float v10 = acc[mt][nt][2] * a0 + b0;
            float v11 = acc[mt][nt][3] * a1 + b1;
            if (MODE < 2) {
                v00 = fmaxf(v00, 0.f); v01 = fmaxf(v01, 0.f);
                v10 = fmaxf(v10, 0.f); v11 = fmaxf(v11, 0.f);
            }
            if (MODE == 0) {
                __nv_bfloat16 h00 = __float2bfloat16(v00), h01 = __float2bfloat16(v01);
                __nv_bfloat16 h10 = __float2bfloat16(v10), h11 = __float2bfloat16(v11);
                __nv_bfloat16 l00 = __float2bfloat16(v00 - __bfloat162float(h00));
                __nv_bfloat16 l01 = __float2bfloat16(v01 - __bfloat162float(h01));
                __nv_bfloat16 l10 = __float2bfloat16(v10 - __bfloat162float(h10));
                __nv_bfloat16 l11 = __float2bfloat16(v11 - __bfloat162float(h11));
                if (r0 < n) {
                    *(uint32_t*)(g_bhi + (size_t)r0 * 128 + c) = bfpack(h00, h01);
                    *(uint32_t*)(g_blo + (size_t)r0 * 128 + c) = bfpack(l00, l01);
                }
                if (r1 < n) {
                    *(uint32_t*)(g_bhi + (size_t)r1 * 128 + c) = bfpack(h10, h11);
                    *(uint32_t*)(g_blo + (size_t)r1 * 128 + c) = bfpack(l10, l11);
                }
            } else {
                if (r0 < n) *(float2*)(outF + (size_t)r0 * 128 + c) = make_float2(v00, v01);
                if (r1 < n) *(float2*)(outF + (size_t)r1 * 128 + c) = make_float2(v10, v11);
            }
        }
    }
}

// ================= pooling =================
__global__ void pool_k() {
    int g = blockIdx.x;
    int tid = threadIdx.x;   // 128
    int s = g_goff[g];
    int e = g_goff[g + 1];
    float a1 = 0.f, a2 = 0.f, a3 = 0.f;
    for (int i = s; i < e; i++) {
        a1 += g_x1[i * 128 + tid];
        a2 += g_x2[i * 128 + tid];
        a3 += g_x3[i * 128 + tid];
    }
    float inv = 1.0f / (float)max(e - s, 1);
    g_pooled[g * 384 + tid]       = a1 * inv;
    g_pooled[g * 384 + 128 + tid] = a2 * inv;
    g_pooled[g * 384 + 256 + tid] = a3 * inv;
}

// ================= final linear =================
__global__ void fin_k(const float* __restrict__ W, const float* __restrict__ b,
                      float* __restrict__ out) {
    __shared__ float p[384];
    int g = blockIdx.x;
    int tid = threadIdx.x;   // 128
    for (int i = tid; i < 384; i += 128) p[i] = g_pooled[g * 384 + i];
    __syncthreads();
    float acc = b[tid];
#pragma unroll 4
    for (int k = 0; k < 384; k++) acc += p[k] * W[k * 128 + tid];
    out[g * 128 + tid] = acc;
}

// ================= launch =================
extern "C" void kernel_launch(void* const* d_in, const int* in_sizes, int n_in,
                              void* d_out, int out_size) {
    const float* x     = (const float*)d_in[0];
    const int*   ei    = (const int*)d_in[1];
    const int*   batch = (const int*)d_in[2];
    float* out = (float*)d_out;

    const float* L[3][8];
    for (int l = 0; l < 3; l++)
        for (int k = 0; k < 8; k++)
            L[l][k] = (const float*)d_in[3 + l * 8 + k];
    const float* linW = (const float*)d_in[27];
    const float* linB = (const float*)d_in[28];

    const int SMEM = 2 * 128 * SW * 2 + 2 * 128 * SA * 2;   // 69632 + 20480 = 90112
    cudaFuncSetAttribute(gemm_tc_k<0>, cudaFuncAttributeMaxDynamicSharedMemorySize, SMEM);
    cudaFuncSetAttribute(gemm_tc_k<1>, cudaFuncAttributeMaxDynamicSharedMemorySize, SMEM);
    cudaFuncSetAttribute(gemm_tc_k<2>, cudaFuncAttributeMaxDynamicSharedMemorySize, SMEM);

    const int GGRID = (NN + 127) / 128;   // 391

    zero_k<<<(NN + 255) / 256, 256>>>();
    hist_dst_k<<<(EE + 255) / 256, 256>>>(ei);
    scan_k<0><<<1, 1024>>>(NN);
    fill_csr_k<<<(EE + 255) / 256, 256>>>(ei);
    hist_batch_k<<<(NN + 255) / 256, 256>>>(batch);
    scan_k<1><<<1, 1024>>>(GG);
    prep_w_k<<<6, 256>>>(L[0][0], L[0][6], L[1][0], L[1][6], L[2][0], L[2][6]);

    // layer 1: agg(x) -> pair A; G1 -> pair B; G2 -> x1
    aggregate_k<<<(NN + 7) / 8, 256>>>(x, -1);
    gemm_tc_k<0><<<GGRID, 256, SMEM>>>(0, 0, 0, L[0][1], L[0][2], L[0][3], L[0][4], L[0][5], NN);
    gemm_tc_k<1><<<GGRID, 256, SMEM>>>(1, 1, 1, L[0][7], nullptr, nullptr, nullptr, nullptr, NN);
    // layer 2
    aggregate_k<<<(NN + 7) / 8, 256>>>(nullptr, 1);
    gemm_tc_k<0><<<GGRID, 256, SMEM>>>(0, 0, 2, L[1][1], L[1][2], L[1][3], L[1][4], L[1][5], NN);
    gemm_tc_k<1><<<GGRID, 256, SMEM>>>(1, 2, 3, L[1][7], nullptr, nullptr, nullptr, nullptr, NN);
    // layer 3 (no outer ReLU)
    aggregate_k<<<(NN + 7) / 8, 256>>>(nullptr, 2);
    gemm_tc_k<0><<<GGRID, 256, SMEM>>>(0, 0, 4, L[2][1], L[2][2], L[2][3], L[2][4], L[2][5], NN);
    gemm_tc_k<2><<<GGRID, 256, SMEM>>>(1, 3, 5, L[2][7], nullptr, nullptr, nullptr, nullptr, NN);

    pool_k<<<GG, 128>>>();
    fin_k<<<GG, 128>>>(linW, linB, out);
}

// round 7
// speedup vs baseline: 1.8423x; 1.1660x over previous
#include <cuda_runtime.h>
#include <cuda_bf16.h>
#include <cstdint>

#define NN 50000
#define EE 600000
#define GG 512
#define BN_EPS 1e-5f
#define NBLK 196    // ceil(NN/256)

// ================= scratch (device globals; allocation-free) =================
__device__ int   g_counts[NN];
__device__ int   g_cursor[NN];
__device__ int   g_offsets[NN + 1];
__device__ int   g_csr[EE];
__device__ int   g_goff[GG + 1];
__device__ int   g_bsums[NBLK], g_bpre[NBLK];
__device__ __nv_bfloat16 g_ahi[NN * 128], g_alo[NN * 128];   // GEMM1 input pair
__device__ __nv_bfloat16 g_bhi[NN * 128], g_blo[NN * 128];   // GEMM2 input pair
__device__ float g_x1[NN * 128], g_x2[NN * 128], g_x3[NN * 128];
__device__ float g_pooled[GG * 384];
// transposed hi/lo weights: g_wh[m][n*128+k] = hi(W_m[k][n])
__device__ __nv_bfloat16 g_wh[6 * 16384], g_wl[6 * 16384];

// device-side buffer resolution (NEVER pass __device__ symbols from host!)
__device__ __forceinline__ float* xbuf(int s) {
    return (s == 1) ? g_x1 : (s == 2) ? g_x2 : g_x3;
}

__device__ __forceinline__ uint32_t bfpack(__nv_bfloat16 a, __nv_bfloat16 b) {
    return (uint32_t)__bfloat16_as_ushort(a) | ((uint32_t)__bfloat16_as_ushort(b) << 16);
}

__device__ __forceinline__ uint32_t smem_u32(const void* p) {
    uint32_t a;
    asm("{ .reg .u64 t; cvta.to.shared.u64 t, %1; cvt.u32.u64 %0, t; }" : "=r"(a) : "l"(p));
    return a;
}

// cp.async 16B with zero-fill when pbytes=0
__device__ __forceinline__ void cp16z(uint32_t dst, const void* src, int pbytes) {
    asm volatile("cp.async.cg.shared.global [%0], [%1], 16, %2;" :: "r"(dst), "l"(src), "r"(pbytes) : "memory");
}
__device__ __forceinline__ void cp16(uint32_t dst, const void* src) {
    asm volatile("cp.async.cg.shared.global [%0], [%1], 16;" :: "r"(dst), "l"(src) : "memory");
}
#define CP_COMMIT() asm volatile("cp.async.commit_group;" ::: "memory")
#define CP_WAIT0()  asm volatile("cp.async.wait_group 0;" ::: "memory")
#define CP_WAIT1()  asm volatile("cp.async.wait_group 1;" ::: "memory")

// mma.sync m16n8k16 bf16 -> f32 accumulate
__device__ __forceinline__ void mma16816(float* c, const uint32_t* a, uint32_t b0, uint32_t b1) {
    asm volatile(
        "mma.sync.aligned.m16n8k16.row.col.f32.bf16.bf16.f32 "
        "{%0,%1,%2,%3}, {%4,%5,%6,%7}, {%8,%9}, {%0,%1,%2,%3};"
        : "+f"(c[0]), "+f"(c[1]), "+f"(c[2]), "+f"(c[3])
        : "r"(a[0]), "r"(a[1]), "r"(a[2]), "r"(a[3]), "r"(b0), "r"(b1));
}

// ================= CSR build =================
__global__ void zero_k() {
    int i = blockIdx.x * blockDim.x + threadIdx.x;
    if (i < NN) { g_counts[i] = 0; g_cursor[i] = 0; }
}
__global__ void hist_dst_k(const int* __restrict__ ei) {
    int e = blockIdx.x * blockDim.x + threadIdx.x;
    if (e < EE) atomicAdd(&g_counts[ei[EE + e]], 1);
}

// 3-phase multi-block exclusive scan of g_counts -> g_offsets
__global__ void scan_blocksum_k() {
    __shared__ int sh[256];
    int tid = threadIdx.x;
    int i = blockIdx.x * 256 + tid;
    sh[tid] = (i < NN) ? g_counts[i] : 0;
    __syncthreads();
    for (int off = 128; off > 0; off >>= 1) {
        if (tid < off) sh[tid] += sh[tid + off];
        __syncthreads();
    }
    if (tid == 0) g_bsums[blockIdx.x] = sh[0];
}
__global__ void scan_top_k() {
    __shared__ int sh[256];
    int tid = threadIdx.x;
    int v = (tid < NBLK) ? g_bsums[tid] : 0;
    sh[tid] = v;
    __syncthreads();
    for (int off = 1; off < 256; off <<= 1) {
        int t = (tid >= off) ? sh[tid - off] : 0;
        __syncthreads();
        sh[tid] += t;
        __syncthreads();
    }
    if (tid < NBLK) g_bpre[tid] = sh[tid] - v;
    if (tid == NBLK - 1) g_offsets[NN] = sh[tid];
}
__global__ void scan_apply_k() {
    __shared__ int sh[256];
    int tid = threadIdx.x;
    int i = blockIdx.x * 256 + tid;
    int v = (i < NN) ? g_counts[i] : 0;
    sh[tid] = v;
    __syncthreads();
    for (int off = 1; off < 256; off <<= 1) {
        int t = (tid >= off) ? sh[tid - off] : 0;
        __syncthreads();
        sh[tid] += t;
        __syncthreads();
    }
    if (i < NN) g_offsets[i] = g_bpre[blockIdx.x] + sh[tid] - v;
}

__global__ void fill_csr_k(const int* __restrict__ ei) {
    int e = blockIdx.x * blockDim.x + threadIdx.x;
    if (e < EE) {
        int s = ei[e];
        int d = ei[EE + e];
        int pos = atomicAdd(&g_cursor[d], 1);
        g_csr[g_offsets[d] + pos] = s;
    }
}

// graph segment offsets via lower_bound on sorted batch
__global__ void goff_k(const int* __restrict__ batch) {
    int g = blockIdx.x * blockDim.x + threadIdx.x;
    if (g > GG) return;
    int lo = 0, hi = NN;
    while (lo < hi) {
        int mid = (lo + hi) >> 1;
        if (batch[mid] < g) lo = mid + 1; else hi = mid;
    }
    g_goff[g] = lo;
}

// ================= weight prep: transpose + hi/lo split =================
__global__ void prep_w_k(const float* w0, const float* w1, const float* w2,
                         const float* w3, const float* w4, const float* w5) {
    const float* Ws[6] = {w0, w1, w2, w3, w4, w5};
    int m = blockIdx.x;
    const float* W = Ws[m];
    for (int i = threadIdx.x; i < 16384; i += blockDim.x) {
        int n = i >> 7;          // output column (B row)
        int k = i & 127;         // contraction
        float v = W[k * 128 + n];
        __nv_bfloat16 hi = __float2bfloat16(v);
        __nv_bfloat16 lo = __float2bfloat16(v - __bfloat162float(hi));
        g_wh[m * 16384 + i] = hi;
        g_wl[m * 16384 + i] = lo;
    }
}

// ================= aggregation: pair = split(x[i] + sum_{j in N(i)} x[j]) =================
__global__ void aggregate_k(const float* __restrict__ xext, int sel) {
    int node = blockIdx.x * 8 + (threadIdx.x >> 5);
    int lane = threadIdx.x & 31;
    if (node >= NN) return;
    const float* x = (sel < 0) ? xext : xbuf(sel);
    const float4* x4 = (const float4*)x;
    float4 acc = x4[node * 32 + lane];
    int s = g_offsets[node];
    int e = g_offsets[node + 1];
    int p = s;
    // unroll-by-4: 4 independent gathers in flight
    for (; p + 4 <= e; p += 4) {
        int i0 = g_csr[p], i1 = g_csr[p + 1], i2 = g_csr[p + 2], i3 = g_csr[p + 3];
        float4 v0 = __ldg(&x4[i0 * 32 + lane]);
        float4 v1 = __ldg(&x4[i1 * 32 + lane]);
        float4 v2 = __ldg(&x4[i2 * 32 + lane]);
        float4 v3 = __ldg(&x4[i3 * 32 + lane]);
        acc.x += v0.x + v1.x + v2.x + v3.x;
        acc.y += v0.y + v1.y + v2.y + v3.y;
        acc.z += v0.z + v1.z + v2.z + v3.z;
        acc.w += v0.w + v1.w + v2.w + v3.w;
    }
    for (; p < e; p++) {
        float4 v = __ldg(&x4[g_csr[p] * 32 + lane]);
        acc.x += v.x; acc.y += v.y; acc.z += v.z; acc.w += v.w;
    }
    float vv[4] = {acc.x, acc.y, acc.z, acc.w};
    __nv_bfloat16 h[4], l[4];
#pragma unroll
    for (int j = 0; j < 4; j++) {
        h[j] = __float2bfloat16(vv[j]);
        l[j] = __float2bfloat16(vv[j] - __bfloat162float(h[j]));
    }
    int base = node * 128 + lane * 4;
    *(uint2*)(g_ahi + base) = make_uint2(bfpack(h[0], h[1]), bfpack(h[2], h[3]));
    *(uint2*)(g_alo + base) = make_uint2(bfpack(l[0], l[1]), bfpack(l[2], l[3]));
}

// ================= tensor-core GEMM (cp.async pipelined) =================
// D[128x128] = Ahi@Wh + Ahi@Wl + Alo@Wh  (fp32 accum), per-CTA row tile of 128.
// inSel: 0 -> (g_ahi, g_alo), 1 -> (g_bhi, g_blo)
// MODE 0: BN fold + ReLU -> writes bf16 pair (g_bhi, g_blo)
// MODE 1: +bias, ReLU    -> writes fp32 xbuf(outSel)
// MODE 2: +bias          -> writes fp32 xbuf(outSel)
#define SW 136   // W smem stride (bf16)
#define SA 40    // A smem stride (bf16)
// smem layout (bytes): Wh 0, Wl 34816, A0h 69632, A0l 79872, A1h 90112, A1l 100352; total 110592
#define OFF_WH  0
#define OFF_WL  34816
#define OFF_A0H 69632
#define OFF_A0L 79872
#define OFF_A1H 90112
#define OFF_A1L 100352
#define GSMEM   110592

template <int MODE>
__global__ __launch_bounds__(256, 2) void gemm_tc_k(
    int inSel, int outSel, int wsel,
    const float* __restrict__ p0, const float* __restrict__ p1,
    const float* __restrict__ p2, const float* __restrict__ p3,
    const float* __restrict__ p4, int n)
{
    extern __shared__ char dyn[];
    __shared__ float s_alpha[128], s_beta[128];

    const __nv_bfloat16* Ahi = inSel ? g_bhi : g_ahi;
    const __nv_bfloat16* Alo = inSel ? g_blo : g_alo;
    float* outF = (MODE == 0) ? nullptr : xbuf(outSel);

    int tid = threadIdx.x;
    int lane = tid & 31;
    int wid = tid >> 5;
    int warpM = wid & 3;        // 4 row-warps * 32 rows
    int warpN = wid >> 2;       // 2 col-warps * 64 cols
    int blockRow = blockIdx.x * 128;

    uint32_t sbase = smem_u32(dyn);
    const __nv_bfloat16* Whs = (const __nv_bfloat16*)(dyn + OFF_WH);
    const __nv_bfloat16* Wls = (const __nv_bfloat16*)(dyn + OFF_WL);
    const uint32_t aOffH[2] = {OFF_A0H, OFF_A1H};
    const uint32_t aOffL[2] = {OFF_A0L, OFF_A1L};

    int r = tid >> 1;           // staging row 0..127
    int h = tid & 1;            // half selector
    int grow = blockRow + r;
    int pb = (grow < n) ? 16 : 0;

    // ---- prologue: async-stage W + chunk0 (group0), chunk1 (group1) ----
    {
        const char* whSrc = (const char*)(g_wh + wsel * 16384 + r * 128 + h * 64);
        const char* wlSrc = (const char*)(g_wl + wsel * 16384 + r * 128 + h * 64);
        uint32_t dW = sbase + r * (SW * 2) + h * 128;
#pragma unroll
        for (int i = 0; i < 8; i++) {
            cp16(dW + OFF_WH + i * 16, whSrc + i * 16);
            cp16(dW + OFF_WL + i * 16, wlSrc + i * 16);
        }
        // chunk 0 -> buf 0
        const char* sh0 = (const char*)(Ahi + (size_t)grow * 128 + 0 * 32 + h * 16);
        const char* sl0 = (const char*)(Alo + (size_t)grow * 128 + 0 * 32 + h * 16);
        uint32_t dA = sbase + r * (SA * 2) + h * 32;
        cp16z(dA + OFF_A0H, sh0, pb);      cp16z(dA + OFF_A0H + 16, sh0 + 16, pb);
        cp16z(dA + OFF_A0L, sl0, pb);      cp16z(dA + OFF_A0L + 16, sl0 + 16, pb);
        CP_COMMIT();
        // chunk 1 -> buf 1
        const char* sh1 = (const char*)(Ahi + (size_t)grow * 128 + 1 * 32 + h * 16);
        const char* sl1 = (const char*)(Alo + (size_t)grow * 128 + 1 * 32 + h * 16);
        cp16z(dA + OFF_A1H, sh1, pb);      cp16z(dA + OFF_A1H + 16, sh1 + 16, pb);
        cp16z(dA + OFF_A1L, sl1, pb);      cp16z(dA + OFF_A1L + 16, sl1 + 16, pb);
        CP_COMMIT();
    }
    if (tid < 128) {
        if (MODE == 0) {
            float s = rsqrtf(p4[tid] + BN_EPS);
            float a = p1[tid] * s;
            s_alpha[tid] = a;
            s_beta[tid] = (p0[tid] - p3[tid]) * a + p2[tid];
        } else {
            s_alpha[tid] = 1.f;
            s_beta[tid] = p0[tid];
        }
    }

    float acc[2][8][4];
#pragma unroll
    for (int mt = 0; mt < 2; mt++)
#pragma unroll
        for (int nt = 0; nt < 8; nt++)
#pragma unroll
            for (int q = 0; q < 4; q++) acc[mt][nt][q] = 0.f;

    for (int kc = 0; kc < 4; kc++) {
        if (kc < 3) CP_WAIT1(); else CP_WAIT0();
        __syncthreads();
        int bsel = kc & 1;
        const __nv_bfloat16* Ahs = (const __nv_bfloat16*)(dyn + aOffH[bsel]);
        const __nv_bfloat16* Als = (const __nv_bfloat16*)(dyn + aOffL[bsel]);

#pragma unroll
        for (int ks = 0; ks < 2; ks++) {
            int kk = ks * 16 + (lane & 3) * 2;     // chunk-local k for A frags
            uint32_t ah[2][4], al[2][4];
#pragma unroll
            for (int mt = 0; mt < 2; mt++) {
                int rr = warpM * 32 + mt * 16 + (lane >> 2);
                ah[mt][0] = *(const uint32_t*)&Ahs[rr * SA + kk];
                ah[mt][1] = *(const uint32_t*)&Ahs[(rr + 8) * SA + kk];
                ah[mt][2] = *(const uint32_t*)&Ahs[rr * SA + kk + 8];
                ah[mt][3] = *(const uint32_t*)&Ahs[(rr + 8) * SA + kk + 8];
                al[mt][0] = *(const uint32_t*)&Als[rr * SA + kk];
                al[mt][1] = *(const uint32_t*)&Als[(rr + 8) * SA + kk];
                al[mt][2] = *(const uint32_t*)&Als[rr * SA + kk + 8];
                al[mt][3] = *(const uint32_t*)&Als[(rr + 8) * SA + kk + 8];
            }
            int kg = kc * 32 + ks * 16 + (lane & 3) * 2;   // global k for B frags
#pragma unroll
            for (int nt = 0; nt < 8; nt++) {
                int nr = warpN * 64 + nt * 8 + (lane >> 2);
                uint32_t bh0 = *(const uint32_t*)&Whs[nr * SW + kg];
                uint32_t bh1 = *(const uint32_t*)&Whs[nr * SW + kg + 8];
                uint32_t bl0 = *(const uint32_t*)&Wls[nr * SW + kg];
                uint32_t bl1 = *(const uint32_t*)&Wls[nr * SW + kg + 8];
#pragma unroll
                for (int mt = 0; mt < 2; mt++) {
                    mma16816(acc[mt][nt], ah[mt], bh0, bh1);
                    mma16816(acc[mt][nt], ah[mt], bl0, bl1);
                    mma16816(acc[mt][nt], al[mt], bh0, bh1);
                }
            }
        }
        __syncthreads();
        if (kc < 2) {
            // prefetch chunk kc+2 into buf kc&1
            int kn = kc + 2;
            const char* shN = (const char*)(Ahi + (size_t)grow * 128 + kn * 32 + h * 16);
            const char* slN = (const char*)(Alo + (size_t)grow * 128 + kn * 32 + h * 16);
            uint32_t dA = sbase + r * (SA * 2) + h * 32;
            cp16z(dA + aOffH[kc & 1], shN, pb);  cp16z(dA + aOffH[kc & 1] + 16, shN + 16, pb);
            cp16z(dA + aOffL[kc & 1], slN, pb);  cp16z(dA + aOffL[kc & 1] + 16, slN + 16, pb);
            CP_COMMIT();
        }
    }

    // ---- epilogue ----
#pragma unroll
    for (int mt = 0; mt < 2; mt++) {
        int r0 = blockRow + warpM * 32 + mt * 16 + (lane >> 2);
        int r1 = r0 + 8;
#pragma unroll
        for (int nt = 0; nt < 8; nt++) {
            int c = warpN * 64 + nt * 8 + (lane & 3) * 2;
            float a0 = s_alpha[c], a1 = s_alpha[c + 1];
            float b0 = s_beta[c],  b1 = s_beta[c + 1];
            float v00 = acc[mt][nt][0] * a0 + b0;
            float v01 = acc[mt][nt][1] * a1 + b1;
            float v10 = acc[mt][nt][2] * a0 + b0;
            float v11 = acc[mt][nt][3] * a1 + b1;
            if (MODE < 2) {
                v00 = fmaxf(v00, 0.f); v01 = fmaxf(v01, 0.f);
                v10 = fmaxf(v10, 0.f); v11 = fmaxf(v11, 0.f);
            }
            if (MODE == 0) {
                __nv_bfloat16 h00 = __float2bfloat16(v00), h01 = __float2bfloat16(v01);
                __nv_bfloat16 h10 = __float2bfloat16(v10), h11 = __float2bfloat16(v11);
                __nv_bfloat16 l00 = __float2bfloat16(v00 - __bfloat162float(h00));
                __nv_bfloat16 l01 = __float2bfloat16(v01 - __bfloat162float(h01));
                __nv_bfloat16 l10 = __float2bfloat16(v10 - __bfloat162float(h10));
                __nv_bfloat16 l11 = __float2bfloat16(v11 - __bfloat162float(h11));
                if (r0 < n) {
                    *(uint32_t*)(g_bhi + (size_t)r0 * 128 + c) = bfpack(h00, h01);
                    *(uint32_t*)(g_blo + (size_t)r0 * 128 + c) = bfpack(l00, l01);
                }
                if (r1 < n) {
                    *(uint32_t*)(g_bhi + (size_t)r1 * 128 + c) = bfpack(h10, h11);
                    *(uint32_t*)(g_blo + (size_t)r1 * 128 + c) = bfpack(l10, l11);
                }
            } else {
                if (r0 < n) *(float2*)(outF + (size_t)r0 * 128 + c) = make_float2(v00, v01);
                if (r1 < n) *(float2*)(outF + (size_t)r1 * 128 + c) = make_float2(v10, v11);
            }
        }
    }
}

// ================= pooling =================
__global__ void pool_k() {
    int g = blockIdx.x;
    int tid = threadIdx.x;   // 128
    int s = g_goff[g];
    int e = g_goff[g + 1];
    float a1 = 0.f, a2 = 0.f, a3 = 0.f;
    for (int i = s; i < e; i++) {
        a1 += g_x1[i * 128 + tid];
        a2 += g_x2[i * 128 + tid];
        a3 += g_x3[i * 128 + tid];
    }
    float inv = 1.0f / (float)max(e - s, 1);
    g_pooled[g * 384 + tid]       = a1 * inv;
    g_pooled[g * 384 + 128 + tid] = a2 * inv;
    g_pooled[g * 384 + 256 + tid] = a3 * inv;
}

// ================= final linear =================
__global__ void fin_k(const float* __restrict__ W, const float* __restrict__ b,
                      float* __restrict__ out) {
    __shared__ float p[384];
    int g = blockIdx.x;
    int tid = threadIdx.x;   // 128
    for (int i = tid; i < 384; i += 128) p[i] = g_pooled[g * 384 + i];
    __syncthreads();
    float acc = b[tid];
#pragma unroll 4
    for (int k = 0; k < 384; k++) acc += p[k] * W[k * 128 + tid];
    out[g * 128 + tid] = acc;
}

// ================= launch =================
extern "C" void kernel_launch(void* const* d_in, const int* in_sizes, int n_in,
                              void* d_out, int out_size) {
    const float* x     = (const float*)d_in[0];
    const int*   ei    = (const int*)d_in[1];
    const int*   batch = (const int*)d_in[2];
    float* out = (float*)d_out;

    const float* L[3][8];
    for (int l = 0; l < 3; l++)
        for (int k = 0; k < 8; k++)
            L[l][k] = (const float*)d_in[3 + l * 8 + k];
    const float* linW = (const float*)d_in[27];
    const float* linB = (const float*)d_in[28];

    cudaFuncSetAttribute(gemm_tc_k<0>, cudaFuncAttributeMaxDynamicSharedMemorySize, GSMEM);
    cudaFuncSetAttribute(gemm_tc_k<1>, cudaFuncAttributeMaxDynamicSharedMemorySize, GSMEM);
    cudaFuncSetAttribute(gemm_tc_k<2>, cudaFuncAttributeMaxDynamicSharedMemorySize, GSMEM);

    const int GGRID = (NN + 127) / 128;   // 391

    zero_k<<<(NN + 255) / 256, 256>>>();
    hist_dst_k<<<(EE + 255) / 256, 256>>>(ei);
    scan_blocksum_k<<<NBLK, 256>>>();
    scan_top_k<<<1, 256>>>();
    scan_apply_k<<<NBLK, 256>>>();
    fill_csr_k<<<(EE + 255) / 256, 256>>>(ei);
    goff_k<<<3, 256>>>(batch);
    prep_w_k<<<6, 256>>>(L[0][0], L[0][6], L[1][0], L[1][6], L[2][0], L[2][6]);

    // layer 1: agg(x) -> pair A; G1 -> pair B; G2 -> x1
    aggregate_k<<<(NN + 7) / 8, 256>>>(x, -1);
    gemm_tc_k<0><<<GGRID, 256, GSMEM>>>(0, 0, 0, L[0][1], L[0][2], L[0][3], L[0][4], L[0][5], NN);
    gemm_tc_k<1><<<GGRID, 256, GSMEM>>>(1, 1, 1, L[0][7], nullptr, nullptr, nullptr, nullptr, NN);
    // layer 2
    aggregate_k<<<(NN + 7) / 8, 256>>>(nullptr, 1);
    gemm_tc_k<0><<<GGRID, 256, GSMEM>>>(0, 0, 2, L[1][1], L[1][2], L[1][3], L[1][4], L[1][5], NN);
    gemm_tc_k<1><<<GGRID, 256, GSMEM>>>(1, 2, 3, L[1][7], nullptr, nullptr, nullptr, nullptr, NN);
    // layer 3 (no outer ReLU)
    aggregate_k<<<(NN + 7) / 8, 256>>>(nullptr, 2);
    gemm_tc_k<0><<<GGRID, 256, GSMEM>>>(0, 0, 4, L[2][1], L[2][2], L[2][3], L[2][4], L[2][5], NN);
    gemm_tc_k<2><<<GGRID, 256, GSMEM>>>(1, 3, 5, L[2][7], nullptr, nullptr, nullptr, nullptr, NN);

    pool_k<<<GG, 128>>>();
    fin_k<<<GG, 128>>>(linW, linB, out);
}

// round 8
// speedup vs baseline: 2.0977x; 1.1386x over previous
#include <cuda_runtime.h>
#include <cuda_bf16.h>
#include <cstdint>

#define NN 50000
#define EE 600000
#define GG 512
#define BN_EPS 1e-5f
#define NBLK 196    // ceil(NN/256)

// ================= scratch (device globals; allocation-free) =================
__device__ int   g_counts[NN];
__device__ int   g_cursor[NN];
__device__ int   g_offsets[NN + 1];
__device__ int   g_csr[EE];
__device__ int   g_goff[GG + 1];
__device__ int   g_bsums[NBLK], g_bpre[NBLK];
__device__ __nv_bfloat16 g_ahi[NN * 128], g_alo[NN * 128];   // layer input pair
__device__ float g_x1[NN * 128], g_x2[NN * 128], g_x3[NN * 128];
__device__ float g_pooled[GG * 384];
// transposed hi/lo weights: g_wh[m][n*128+k] = hi(W_m[k][n])
__device__ __nv_bfloat16 g_wh[6 * 16384], g_wl[6 * 16384];

__device__ __forceinline__ float* xbuf(int s) {
    return (s == 1) ? g_x1 : (s == 2) ? g_x2 : g_x3;
}

__device__ __forceinline__ uint32_t bfpack(__nv_bfloat16 a, __nv_bfloat16 b) {
    return (uint32_t)__bfloat16_as_ushort(a) | ((uint32_t)__bfloat16_as_ushort(b) << 16);
}

__device__ __forceinline__ uint32_t smem_u32(const void* p) {
    uint32_t a;
    asm("{ .reg .u64 t; cvta.to.shared.u64 t, %1; cvt.u32.u64 %0, t; }" : "=r"(a) : "l"(p));
    return a;
}

__device__ __forceinline__ void cp16z(uint32_t dst, const void* src, int pbytes) {
    asm volatile("cp.async.cg.shared.global [%0], [%1], 16, %2;" :: "r"(dst), "l"(src), "r"(pbytes) : "memory");
}
__device__ __forceinline__ void cp16(uint32_t dst, const void* src) {
    asm volatile("cp.async.cg.shared.global [%0], [%1], 16;" :: "r"(dst), "l"(src) : "memory");
}
#define CP_COMMIT() asm volatile("cp.async.commit_group;" ::: "memory")
template <int N>
__device__ __forceinline__ void cp_wait() {
    asm volatile("cp.async.wait_group %0;" :: "n"(N) : "memory");
}

__device__ __forceinline__ void mma16816(float* c, const uint32_t* a, uint32_t b0, uint32_t b1) {
    asm volatile(
        "mma.sync.aligned.m16n8k16.row.col.f32.bf16.bf16.f32 "
        "{%0,%1,%2,%3}, {%4,%5,%6,%7}, {%8,%9}, {%0,%1,%2,%3};"
        : "+f"(c[0]), "+f"(c[1]), "+f"(c[2]), "+f"(c[3])
        : "r"(a[0]), "r"(a[1]), "r"(a[2]), "r"(a[3]), "r"(b0), "r"(b1));
}

// ================= preprocessing (fused: weight prep + goff + zero) =================
__global__ void prep_all_k(const float* w0, const float* w1, const float* w2,
                           const float* w3, const float* w4, const float* w5,
                           const int* __restrict__ batch) {
    int bid = blockIdx.x;
    int tid = threadIdx.x;
    if (bid < 6) {
        const float* Ws[6] = {w0, w1, w2, w3, w4, w5};
        const float* W = Ws[bid];
        for (int i = tid; i < 16384; i += 256) {
            int n = i >> 7, k = i & 127;
            float v = W[k * 128 + n];
            __nv_bfloat16 hi = __float2bfloat16(v);
            __nv_bfloat16 lo = __float2bfloat16(v - __bfloat162float(hi));
            g_wh[bid * 16384 + i] = hi;
            g_wl[bid * 16384 + i] = lo;
        }
    } else if (bid < 9) {
        int g = (bid - 6) * 256 + tid;
        if (g <= GG) {
            int lo = 0, hi = NN;
            while (lo < hi) {
                int mid = (lo + hi) >> 1;
                if (batch[mid] < g) lo = mid + 1; else hi = mid;
            }
            g_goff[g] = lo;
        }
    } else {
        int i = (bid - 9) * 256 + tid;
        if (i < NN) { g_counts[i] = 0; g_cursor[i] = 0; }
    }
}

// ================= CSR build =================
__global__ void hist_dst_k(const int* __restrict__ ei) {
    int e = blockIdx.x * blockDim.x + threadIdx.x;
    if (e < EE) atomicAdd(&g_counts[ei[EE + e]], 1);
}
__global__ void scan_blocksum_k() {
    __shared__ int sh[256];
    int tid = threadIdx.x;
    int i = blockIdx.x * 256 + tid;
    sh[tid] = (i < NN) ? g_counts[i] : 0;
    __syncthreads();
    for (int off = 128; off > 0; off >>= 1) {
        if (tid < off) sh[tid] += sh[tid + off];
        __syncthreads();
    }
    if (tid == 0) g_bsums[blockIdx.x] = sh[0];
}
__global__ void scan_top_k() {
    __shared__ int sh[256];
    int tid = threadIdx.x;
    int v = (tid < NBLK) ? g_bsums[tid] : 0;
    sh[tid] = v;
    __syncthreads();
    for (int off = 1; off < 256; off <<= 1) {
        int t = (tid >= off) ? sh[tid - off] : 0;
        __syncthreads();
        sh[tid] += t;
        __syncthreads();
    }
    if (tid < NBLK) g_bpre[tid] = sh[tid] - v;
    if (tid == NBLK - 1) g_offsets[NN] = sh[tid];
}
__global__ void scan_apply_k() {
    __shared__ int sh[256];
    int tid = threadIdx.x;
    int i = blockIdx.x * 256 + tid;
    int v = (i < NN) ? g_counts[i] : 0;
    sh[tid] = v;
    __syncthreads();
    for (int off = 1; off < 256; off <<= 1) {
        int t = (tid >= off) ? sh[tid - off] : 0;
        __syncthreads();
        sh[tid] += t;
        __syncthreads();
    }
    if (i < NN) g_offsets[i] = g_bpre[blockIdx.x] + sh[tid] - v;
}
__global__ void fill_csr_k(const int* __restrict__ ei) {
    int e = blockIdx.x * blockDim.x + threadIdx.x;
    if (e < EE) {
        int s = ei[e];
        int d = ei[EE + e];
        int pos = atomicAdd(&g_cursor[d], 1);
        g_csr[g_offsets[d] + pos] = s;
    }
}

// ================= aggregation =================
__global__ void aggregate_k(const float* __restrict__ xext, int sel) {
    int node = blockIdx.x * 8 + (threadIdx.x >> 5);
    int lane = threadIdx.x & 31;
    if (node >= NN) return;
    const float* x = (sel < 0) ? xext : xbuf(sel);
    const float4* x4 = (const float4*)x;
    float4 acc = x4[node * 32 + lane];
    int s = g_offsets[node];
    int e = g_offsets[node + 1];
    int p = s;
    for (; p + 4 <= e; p += 4) {
        int i0 = g_csr[p], i1 = g_csr[p + 1], i2 = g_csr[p + 2], i3 = g_csr[p + 3];
        float4 v0 = __ldg(&x4[i0 * 32 + lane]);
        float4 v1 = __ldg(&x4[i1 * 32 + lane]);
        float4 v2 = __ldg(&x4[i2 * 32 + lane]);
        float4 v3 = __ldg(&x4[i3 * 32 + lane]);
        acc.x += v0.x + v1.x + v2.x + v3.x;
        acc.y += v0.y + v1.y + v2.y + v3.y;
        acc.z += v0.z + v1.z + v2.z + v3.z;
        acc.w += v0.w + v1.w + v2.w + v3.w;
    }
    for (; p < e; p++) {
        float4 v = __ldg(&x4[g_csr[p] * 32 + lane]);
        acc.x += v.x; acc.y += v.y; acc.z += v.z; acc.w += v.w;
    }
    float vv[4] = {acc.x, acc.y, acc.z, acc.w};
    __nv_bfloat16 h[4], l[4];
#pragma unroll
    for (int j = 0; j < 4; j++) {
        h[j] = __float2bfloat16(vv[j]);
        l[j] = __float2bfloat16(vv[j] - __bfloat162float(h[j]));
    }
    int base = node * 128 + lane * 4;
    *(uint2*)(g_ahi + base) = make_uint2(bfpack(h[0], h[1]), bfpack(h[2], h[3]));
    *(uint2*)(g_alo + base) = make_uint2(bfpack(l[0], l[1]), bfpack(l[2], l[3]));
}

// ================= fused GIN layer: out = epi2( relu(BN(t@W1)) @ W2 ) =================
// OUTER_RELU 1 for layers 1-2, 0 for layer 3.
#define SW 136
#define SA 40
#define OFF_WH   0
#define OFF_WL   34816
#define APOOL    69632                      // 4 hi chunks then 4 lo chunks, 10240B each
#define OFF_AH(c) (APOOL + (c) * 10240)
#define OFF_AL(c) (APOOL + 40960 + (c) * 10240)
#define GSMEM    151552

template <int OUTER_RELU>
__global__ __launch_bounds__(256, 1) void gin_layer_k(
    int w1sel, int w2sel, int outSel,
    const float* __restrict__ b1, const float* __restrict__ gm,
    const float* __restrict__ bt, const float* __restrict__ rm,
    const float* __restrict__ rv, const float* __restrict__ b2, int n)
{
    extern __shared__ char dyn[];
    __shared__ float s_alpha[128], s_beta[128], s_b2[128];

    int tid = threadIdx.x;
    int lane = tid & 31;
    int wid = tid >> 5;
    int warpM = wid & 3;
    int warpN = wid >> 2;
    int blockRow = blockIdx.x * 128;

    uint32_t sbase = smem_u32(dyn);
    const __nv_bfloat16* Whs = (const __nv_bfloat16*)(dyn + OFF_WH);
    const __nv_bfloat16* Wls = (const __nv_bfloat16*)(dyn + OFF_WL);

    int r = tid >> 1;
    int h = tid & 1;
    int grow = blockRow + r;
    int pb = (grow < n) ? 16 : 0;

    // ---- prologue: group0 = W1 + chunk0; groups 1..3 = chunks 1..3 ----
    {
        const char* whSrc = (const char*)(g_wh + w1sel * 16384 + r * 128 + h * 64);
        const char* wlSrc = (const char*)(g_wl + w1sel * 16384 + r * 128 + h * 64);
        uint32_t dW = sbase + r * (SW * 2) + h * 128;
#pragma unroll
        for (int i = 0; i < 8; i++) {
            cp16(dW + OFF_WH + i * 16, whSrc + i * 16);
            cp16(dW + OFF_WL + i * 16, wlSrc + i * 16);
        }
        uint32_t dA = sbase + r * (SA * 2) + h * 32;
        const char* shc = (const char*)(g_ahi + (size_t)grow * 128 + h * 16);
        const char* slc = (const char*)(g_alo + (size_t)grow * 128 + h * 16);
        cp16z(dA + OFF_AH(0), shc, pb);      cp16z(dA + OFF_AH(0) + 16, shc + 16, pb);
        cp16z(dA + OFF_AL(0), slc, pb);      cp16z(dA + OFF_AL(0) + 16, slc + 16, pb);
        CP_COMMIT();
#pragma unroll
        for (int c = 1; c < 4; c++) {
            cp16z(dA + OFF_AH(c), shc + c * 64, pb);  cp16z(dA + OFF_AH(c) + 16, shc + c * 64 + 16, pb);
            cp16z(dA + OFF_AL(c), slc + c * 64, pb);  cp16z(dA + OFF_AL(c) + 16, slc + c * 64 + 16, pb);
            CP_COMMIT();
        }
    }
    if (tid < 128) {
        float s = rsqrtf(rv[tid] + BN_EPS);
        float a = gm[tid] * s;
        s_alpha[tid] = a;
        s_beta[tid] = (b1[tid] - rm[tid]) * a + bt[tid];
        s_b2[tid] = b2[tid];
    }

    float acc[2][8][4];
#pragma unroll
    for (int mt = 0; mt < 2; mt++)
#pragma unroll
        for (int nt = 0; nt < 8; nt++)
#pragma unroll
            for (int q = 0; q < 4; q++) acc[mt][nt][q] = 0.f;

    // ---- mainloop 1 (t @ W1) ----
#pragma unroll
    for (int kc = 0; kc < 4; kc++) {
        switch (kc) {
            case 0: cp_wait<3>(); break;
            case 1: cp_wait<2>(); break;
            case 2: cp_wait<1>(); break;
            default: cp_wait<0>(); break;
        }
        __syncthreads();
        const __nv_bfloat16* Ahs = (const __nv_bfloat16*)(dyn + OFF_AH(kc));
        const __nv_bfloat16* Als = (const __nv_bfloat16*)(dyn + OFF_AL(kc));
#pragma unroll
        for (int ks = 0; ks < 2; ks++) {
            int kk = ks * 16 + (lane & 3) * 2;
            uint32_t ah[2][4], al[2][4];
#pragma unroll
            for (int mt = 0; mt < 2; mt++) {
                int rr = warpM * 32 + mt * 16 + (lane >> 2);
                ah[mt][0] = *(const uint32_t*)&Ahs[rr * SA + kk];
                ah[mt][1] = *(const uint32_t*)&Ahs[(rr + 8) * SA + kk];
                ah[mt][2] = *(const uint32_t*)&Ahs[rr * SA + kk + 8];
                ah[mt][3] = *(const uint32_t*)&Ahs[(rr + 8) * SA + kk + 8];
                al[mt][0] = *(const uint32_t*)&Als[rr * SA + kk];
                al[mt][1] = *(const uint32_t*)&Als[(rr + 8) * SA + kk];
                al[mt][2] = *(const uint32_t*)&Als[rr * SA + kk + 8];
                al[mt][3] = *(const uint32_t*)&Als[(rr + 8) * SA + kk + 8];
            }
            int kg = kc * 32 + ks * 16 + (lane & 3) * 2;
#pragma unroll
            for (int nt = 0; nt < 8; nt++) {
                int nr = warpN * 64 + nt * 8 + (lane >> 2);
                uint32_t bh0 = *(const uint32_t*)&Whs[nr * SW + kg];
                uint32_t bh1 = *(const uint32_t*)&Whs[nr * SW + kg + 8];
                uint32_t bl0 = *(const uint32_t*)&Wls[nr * SW + kg];
                uint32_t bl1 = *(const uint32_t*)&Wls[nr * SW + kg + 8];
#pragma unroll
                for (int mt = 0; mt < 2; mt++) {
                    mma16816(acc[mt][nt], ah[mt], bh0, bh1);
                    mma16816(acc[mt][nt], ah[mt], bl0, bl1);
                    mma16816(acc[mt][nt], al[mt], bh0, bh1);
                }
            }
        }
    }
    __syncthreads();   // everyone done reading W1 + A chunks

    // ---- kick W2 reload into the W region (hidden behind epilogue1) ----
    {
        const char* whSrc = (const char*)(g_wh + w2sel * 16384 + r * 128 + h * 64);
        const char* wlSrc = (const char*)(g_wl + w2sel * 16384 + r * 128 + h * 64);
        uint32_t dW = sbase + r * (SW * 2) + h * 128;
#pragma unroll
        for (int i = 0; i < 8; i++) {
            cp16(dW + OFF_WH + i * 16, whSrc + i * 16);
            cp16(dW + OFF_WL + i * 16, wlSrc + i * 16);
        }
        CP_COMMIT();
    }

    // ---- epilogue1: u = relu(BN(acc)), hi/lo split, store into smem A chunks ----
#pragma unroll
    for (int mt = 0; mt < 2; mt++) {
        int rL0 = warpM * 32 + mt * 16 + (lane >> 2);
        int rL1 = rL0 + 8;
#pragma unroll
        for (int nt = 0; nt < 8; nt++) {
            int c = warpN * 64 + nt * 8 + (lane & 3) * 2;
            int ck = c >> 5, kk = c & 31;
            float a0 = s_alpha[c], a1 = s_alpha[c + 1];
            float b0 = s_beta[c],  b1v = s_beta[c + 1];
            float v00 = fmaxf(acc[mt][nt][0] * a0 + b0, 0.f);
            float v01 = fmaxf(acc[mt][nt][1] * a1 + b1v, 0.f);
            float v10 = fmaxf(acc[mt][nt][2] * a0 + b0, 0.f);
            float v11 = fmaxf(acc[mt][nt][3] * a1 + b1v, 0.f);
            __nv_bfloat16 h00 = __float2bfloat16(v00), h01 = __float2bfloat16(v01);
            __nv_bfloat16 h10 = __float2bfloat16(v10), h11 = __float2bfloat16(v11);
            __nv_bfloat16 l00 = __float2bfloat16(v00 - __bfloat162float(h00));
            __nv_bfloat16 l01 = __float2bfloat16(v01 - __bfloat162float(h01));
            __nv_bfloat16 l10 = __float2bfloat16(v10 - __bfloat162float(h10));
            __nv_bfloat16 l11 = __float2bfloat16(v11 - __bfloat162float(h11));
            *(uint32_t*)(dyn + OFF_AH(ck) + rL0 * (SA * 2) + kk * 2) = bfpack(h00, h01);
            *(uint32_t*)(dyn + OFF_AH(ck) + rL1 * (SA * 2) + kk * 2) = bfpack(h10, h11);
            *(uint32_t*)(dyn + OFF_AL(ck) + rL0 * (SA * 2) + kk * 2) = bfpack(l00, l01);
            *(uint32_t*)(dyn + OFF_AL(ck) + rL1 * (SA * 2) + kk * 2) = bfpack(l10, l11);
            // reset for GEMM2
            acc[mt][nt][0] = 0.f; acc[mt][nt][1] = 0.f;
            acc[mt][nt][2] = 0.f; acc[mt][nt][3] = 0.f;
        }
    }
    cp_wait<0>();      // W2 resident
    __syncthreads();   // u visible to all warps

    // ---- mainloop 2 (u @ W2), all operands smem-resident ----
#pragma unroll
    for (int kc = 0; kc < 4; kc++) {
        const __nv_bfloat16* Ahs = (const __nv_bfloat16*)(dyn + OFF_AH(kc));
        const __nv_bfloat16* Als = (const __nv_bfloat16*)(dyn + OFF_AL(kc));
#pragma unroll
        for (int ks = 0; ks < 2; ks++) {
            int kk = ks * 16 + (lane & 3) * 2;
            uint32_t ah[2][4], al[2][4];
#pragma unroll
            for (int mt = 0; mt < 2; mt++) {
                int rr = warpM * 32 + mt * 16 + (lane >> 2);
                ah[mt][0] = *(const uint32_t*)&Ahs[rr * SA + kk];
                ah[mt][1] = *(const uint32_t*)&Ahs[(rr + 8) * SA + kk];
                ah[mt][2] = *(const uint32_t*)&Ahs[rr * SA + kk + 8];
                ah[mt][3] = *(const uint32_t*)&Ahs[(rr + 8) * SA + kk + 8];
                al[mt][0] = *(const uint32_t*)&Als[rr * SA + kk];
                al[mt][1] = *(const uint32_t*)&Als[(rr + 8) * SA + kk];
                al[mt][2] = *(const uint32_t*)&Als[rr * SA + kk + 8];
                al[mt][3] = *(const uint32_t*)&Als[(rr + 8) * SA + kk + 8];
            }
            int kg = kc * 32 + ks * 16 + (lane & 3) * 2;
#pragma unroll
            for (int nt = 0; nt < 8; nt++) {
                int nr = warpN * 64 + nt * 8 + (lane >> 2);
                uint32_t bh0 = *(const uint32_t*)&Whs[nr * SW + kg];
                uint32_t bh1 = *(const uint32_t*)&Whs[nr * SW + kg + 8];
                uint32_t bl0 = *(const uint32_t*)&Wls[nr * SW + kg];
                uint32_t bl1 = *(const uint32_t*)&Wls[nr * SW + kg + 8];
#pragma unroll
                for (int mt = 0; mt < 2; mt++) {
                    mma16816(acc[mt][nt], ah[mt], bh0, bh1);
                    mma16816(acc[mt][nt], ah[mt], bl0, bl1);
                    mma16816(acc[mt][nt], al[mt], bh0, bh1);
                }
            }
        }
    }

    // ---- epilogue2: out = acc + b2 (+ optional outer ReLU) -> fp32 ----
    float* outF = xbuf(outSel);
#pragma unroll
    for (int mt = 0; mt < 2; mt++) {
        int r0 = blockRow + warpM * 32 + mt * 16 + (lane >> 2);
        int r1 = r0 + 8;
#pragma unroll
        for (int nt = 0; nt < 8; nt++) {
            int c = warpN * 64 + nt * 8 + (lane & 3) * 2;
            float b0 = s_b2[c], b1v = s_b2[c + 1];
            float v00 = acc[mt][nt][0] + b0;
            float v01 = acc[mt][nt][1] + b1v;
            float v10 = acc[mt][nt][2] + b0;
            float v11 = acc[mt][nt][3] + b1v;
            if (OUTER_RELU) {
                v00 = fmaxf(v00, 0.f); v01 = fmaxf(v01, 0.f);
                v10 = fmaxf(v10, 0.f); v11 = fmaxf(v11, 0.f);
            }
            if (r0 < n) *(float2*)(outF + (size_t)r0 * 128 + c) = make_float2(v00, v01);
            if (r1 < n) *(float2*)(outF + (size_t)r1 * 128 + c) = make_float2(v10, v11);
        }
    }
}

// ================= pooling =================
__global__ void pool_k() {
    int g = blockIdx.x;
    int tid = threadIdx.x;   // 128
    int s = g_goff[g];
    int e = g_goff[g + 1];
    float a1 = 0.f, a2 = 0.f, a3 = 0.f;
    for (int i = s; i < e; i++) {
        a1 += g_x1[i * 128 + tid];
        a2 += g_x2[i * 128 + tid];
        a3 += g_x3[i * 128 + tid];
    }
    float inv = 1.0f / (float)max(e - s, 1);
    g_pooled[g * 384 + tid]       = a1 * inv;
    g_pooled[g * 384 + 128 + tid] = a2 * inv;
    g_pooled[g * 384 + 256 + tid] = a3 * inv;
}

// ================= final linear =================
__global__ void fin_k(const float* __restrict__ W, const float* __restrict__ b,
                      float* __restrict__ out) {
    __shared__ float p[384];
    int g = blockIdx.x;
    int tid = threadIdx.x;   // 128
    for (int i = tid; i < 384; i += 128) p[i] = g_pooled[g * 384 + i];
    __syncthreads();
    float acc = b[tid];
#pragma unroll 4
    for (int k = 0; k < 384; k++) acc += p[k] * W[k * 128 + tid];
    out[g * 128 + tid] = acc;
}

// ================= launch =================
extern "C" void kernel_launch(void* const* d_in, const int* in_sizes, int n_in,
                              void* d_out, int out_size) {
    const float* x     = (const float*)d_in[0];
    const int*   ei    = (const int*)d_in[1];
    const int*   batch = (const int*)d_in[2];
    float* out = (float*)d_out;

    const float* L[3][8];
    for (int l = 0; l < 3; l++)
        for (int k = 0; k < 8; k++)
            L[l][k] = (const float*)d_in[3 + l * 8 + k];
    const float* linW = (const float*)d_in[27];
    const float* linB = (const float*)d_in[28];

    cudaFuncSetAttribute(gin_layer_k<1>, cudaFuncAttributeMaxDynamicSharedMemorySize, GSMEM);
    cudaFuncSetAttribute(gin_layer_k<0>, cudaFuncAttributeMaxDynamicSharedMemorySize, GSMEM);

    const int GGRID = (NN + 127) / 128;   // 391

    prep_all_k<<<9 + NBLK, 256>>>(L[0][0], L[0][6], L[1][0], L[1][6], L[2][0], L[2][6], batch);
    hist_dst_k<<<(EE + 255) / 256, 256>>>(ei);
    scan_blocksum_k<<<NBLK, 256>>>();
    scan_top_k<<<1, 256>>>();
    scan_apply_k<<<NBLK, 256>>>();
    fill_csr_k<<<(EE + 255) / 256, 256>>>(ei);

    // layer 1
    aggregate_k<<<(NN + 7) / 8, 256>>>(x, -1);
    gin_layer_k<1><<<GGRID, 256, GSMEM>>>(0, 1, 1, L[0][1], L[0][2], L[0][3], L[0][4], L[0][5], L[0][7], NN);
    // layer 2
    aggregate_k<<<(NN + 7) / 8, 256>>>(nullptr, 1);
    gin_layer_k<1><<<GGRID, 256, GSMEM>>>(2, 3, 2, L[1][1], L[1][2], L[1][3], L[1][4], L[1][5], L[1][7], NN);
    // layer 3 (no outer ReLU)
    aggregate_k<<<(NN + 7) / 8, 256>>>(nullptr, 2);
    gin_layer_k<0><<<GGRID, 256, GSMEM>>>(4, 5, 3, L[2][1], L[2][2], L[2][3], L[2][4], L[2][5], L[2][7], NN);

    pool_k<<<GG, 128>>>();
    fin_k<<<GG, 128>>>(linW, linB, out);
}